// round 16
// baseline (speedup 1.0000x reference)
#include <cuda_runtime.h>

#define BQ 1024
#define NQ 8192
#define DQ 128
#define NSPLIT 8

__device__ int    g_ind[BQ];
__device__ float  g_pbest[NSPLIT][BQ];
__device__ int    g_pbidx[NSPLIT][BQ];
__device__ double g_sx2;
__device__ double g_sq2;
__device__ double g_sxd[DQ];
__device__ double g_sqd[DQ];

// ---------------------------------------------------------------- argmin smem
struct ArgSmem {
    float xt[128][20];        // x transposed [k][row] (pad 20; 80B rows keep 16B align)
    float wt[2][16][256];     // W stage transposed [k][n], double-buffered, K=16
    float Cs[16];
    float wpart[16][2];
    float sb[16][64];
    int   si[16][64];
};
extern __shared__ unsigned char dynsmem[];

// ---------------------------------------------------------------- argmin (SGEMM-style)
// Numerics bit-identical to the passing R13..R15 path: per-output single fp32
// accumulator, FFMA over d=0..127 ascending (8 stages x K=16 per n-tile);
// score = __fsub_rn(C, __fmul_rn(2,acc)); ties -> lowest n; C via the proven
// 64-thread float2/shuffle tree. Single barrier per stage (write the buffer
// not being read). Grid 512 = 64 rowblocks x 8 n-splits; smem ~50KB -> 3-4
// blocks/SM resident for latency hiding.
__global__ void __launch_bounds__(256, 3) k_argmin3(const float* __restrict__ x,
                                                    const float* __restrict__ W) {
    ArgSmem& sm = *reinterpret_cast<ArgSmem*>(dynsmem);
    int rb = blockIdx.x & 63;
    int cs = blockIdx.x >> 6;
    int r0 = rb * 16;
    int nbase = cs * 1024;
    int tid = threadIdx.x;
    int rg = tid >> 6, cg = tid & 63;

    // ---- C for 16 rows (bit-identical tree) ----
    {
        int grp = tid >> 6;
        int t64 = tid & 63;
        #pragma unroll
        for (int pass = 0; pass < 4; pass++) {
            int row16 = pass * 4 + grp;
            const float2* xp = (const float2*)(x + (size_t)(r0 + row16) * DQ);
            float2 v = xp[t64];
            float p = __fadd_rn(__fmul_rn(v.x, v.x), __fmul_rn(v.y, v.y));
            #pragma unroll
            for (int o = 16; o; o >>= 1)
                p = __fadd_rn(p, __shfl_down_sync(0xffffffffu, p, o));
            if ((t64 & 31) == 0) sm.wpart[row16][t64 >> 5] = p;
        }
    }
    for (int i = tid; i < 16 * 128; i += 256) {
        int r = i >> 7, d = i & 127;
        sm.xt[d][r] = x[(size_t)(r0 + r) * DQ + d];
    }
    __syncthreads();
    if (tid < 16) sm.Cs[tid] = __fadd_rn(sm.wpart[tid][0], sm.wpart[tid][1]);
    __syncthreads();

    float best[4];
    int   bidx[4];
    #pragma unroll
    for (int r = 0; r < 4; r++) { best[r] = 3.4e38f; bidx[r] = 0; }

    float acc[4][4];
    float4 rv[4];

    // preload stage u=0: tile 0, k 0..15; thread owns W row nbase+tid
    {
        const float4* wr = (const float4*)(W + (size_t)(nbase + tid) * DQ);
        #pragma unroll
        for (int q = 0; q < 4; q++) rv[q] = wr[q];
        #pragma unroll
        for (int q = 0; q < 4; q++) {
            sm.wt[0][q * 4 + 0][tid] = rv[q].x;
            sm.wt[0][q * 4 + 1][tid] = rv[q].y;
            sm.wt[0][q * 4 + 2][tid] = rv[q].z;
            sm.wt[0][q * 4 + 3][tid] = rv[q].w;
        }
    }
    __syncthreads();

    for (int u = 0; u < 32; u++) {             // u = tile*8 + stage; K-stage = 16
        int t = u >> 3, s = u & 7;
        int buf = u & 1;
        if (s == 0) {
            #pragma unroll
            for (int a = 0; a < 4; a++)
                #pragma unroll
                for (int b = 0; b < 4; b++) acc[a][b] = 0.f;
        }
        if (u < 31) {                          // LDG next stage
            int u1 = u + 1;
            const float4* wr = (const float4*)(W + (size_t)(nbase + (u1 >> 3) * 256 + tid) * DQ
                                               + (u1 & 7) * 16);
            #pragma unroll
            for (int q = 0; q < 4; q++) rv[q] = wr[q];
        }
        #pragma unroll
        for (int kk = 0; kk < 16; kk++) {
            float4 xa = *(const float4*)&sm.xt[s * 16 + kk][rg * 4];
            float4 wb = *(const float4*)&sm.wt[buf][kk][cg * 4];
            acc[0][0] = fmaf(xa.x, wb.x, acc[0][0]);
            acc[0][1] = fmaf(xa.x, wb.y, acc[0][1]);
            acc[0][2] = fmaf(xa.x, wb.z, acc[0][2]);
            acc[0][3] = fmaf(xa.x, wb.w, acc[0][3]);
            acc[1][0] = fmaf(xa.y, wb.x, acc[1][0]);
            acc[1][1] = fmaf(xa.y, wb.y, acc[1][1]);
            acc[1][2] = fmaf(xa.y, wb.z, acc[1][2]);
            acc[1][3] = fmaf(xa.y, wb.w, acc[1][3]);
            acc[2][0] = fmaf(xa.z, wb.x, acc[2][0]);
            acc[2][1] = fmaf(xa.z, wb.y, acc[2][1]);
            acc[2][2] = fmaf(xa.z, wb.z, acc[2][2]);
            acc[2][3] = fmaf(xa.z, wb.w, acc[2][3]);
            acc[3][0] = fmaf(xa.w, wb.x, acc[3][0]);
            acc[3][1] = fmaf(xa.w, wb.y, acc[3][1]);
            acc[3][2] = fmaf(xa.w, wb.z, acc[3][2]);
            acc[3][3] = fmaf(xa.w, wb.w, acc[3][3]);
        }
        if (s == 7) {                          // tile done -> scores + best update
            int n0 = nbase + t * 256;
            #pragma unroll
            for (int ri = 0; ri < 4; ri++) {
                float Cv = sm.Cs[rg * 4 + ri];
                #pragma unroll
                for (int ci = 0; ci < 4; ci++) {
                    float sc = __fsub_rn(Cv, __fmul_rn(2.0f, acc[ri][ci]));
                    int n = n0 + cg * 4 + ci;
                    if (sc < best[ri]) { best[ri] = sc; bidx[ri] = n; }
                }
            }
        }
        if (u < 31) {                          // STS -> buffer NOT being read
            int nb = (u + 1) & 1;
            #pragma unroll
            for (int q = 0; q < 4; q++) {
                sm.wt[nb][q * 4 + 0][tid] = rv[q].x;
                sm.wt[nb][q * 4 + 1][tid] = rv[q].y;
                sm.wt[nb][q * 4 + 2][tid] = rv[q].z;
                sm.wt[nb][q * 4 + 3][tid] = rv[q].w;
            }
        }
        __syncthreads();                       // single barrier per stage
    }

    #pragma unroll
    for (int ri = 0; ri < 4; ri++) {
        sm.sb[rg * 4 + ri][cg] = best[ri];
        sm.si[rg * 4 + ri][cg] = bidx[ri];
    }
    __syncthreads();
    if (tid < 16) {
        float bv = sm.sb[tid][0]; int bi = sm.si[tid][0];
        #pragma unroll 8
        for (int tt = 1; tt < 64; tt++) {
            float v = sm.sb[tid][tt]; int ii = sm.si[tid][tt];
            if (v < bv || (v == bv && ii < bi)) { bv = v; bi = ii; }
        }
        g_pbest[cs][r0 + tid] = bv;
        g_pbidx[cs][r0 + tid] = bi;
    }
}

// ---------------------------------------------------------------- merge + zero
__global__ void __launch_bounds__(1024) k_merge(float* __restrict__ out_ind) {
    int i = threadIdx.x;
    float bv = g_pbest[0][i]; int bi = g_pbidx[0][i];
    #pragma unroll
    for (int cs = 1; cs < NSPLIT; cs++) {
        float v = g_pbest[cs][i]; int ii = g_pbidx[cs][i];
        if (v < bv || (v == bv && ii < bi)) { bv = v; bi = ii; }
    }
    g_ind[i] = bi;
    if (out_ind) out_ind[i] = (float)bi;
    if (i < DQ) { g_sxd[i] = 0.0; g_sqd[i] = 0.0; }
    if (i == 0) { g_sx2 = 0.0; g_sq2 = 0.0; }
}

// ---------------------------------------------------------------- sums (64 blocks)
__global__ void __launch_bounds__(256) k_sums(const float* __restrict__ x,
                                              const float* __restrict__ W) {
    __shared__ double pd[2][DQ];
    __shared__ int sInd[16];
    int r0  = blockIdx.x * 16;
    int tid = threadIdx.x;
    int d = tid & 127, h = tid >> 7;
    if (tid < 16) sInd[tid] = g_ind[r0 + tid];
    __syncthreads();

    double sd = 0.0, s2 = 0.0;
    #pragma unroll
    for (int rr = 0; rr < 8; rr++) {
        double v = (double)x[(size_t)(r0 + h * 8 + rr) * DQ + d];
        sd += v; s2 += v * v;
    }
    pd[h][d] = sd;
    #pragma unroll
    for (int o = 16; o; o >>= 1) s2 += __shfl_down_sync(0xffffffffu, s2, o);
    if ((tid & 31) == 0) atomicAdd(&g_sx2, s2);
    __syncthreads();
    if (tid < DQ) atomicAdd(&g_sxd[tid], pd[0][tid] + pd[1][tid]);
    __syncthreads();

    sd = 0.0; s2 = 0.0;
    #pragma unroll
    for (int rr = 0; rr < 8; rr++) {
        int c = sInd[h * 8 + rr];
        double v = (double)W[(size_t)c * DQ + d];
        sd += v; s2 += v * v;
    }
    pd[h][d] = sd;
    #pragma unroll
    for (int o = 16; o; o >>= 1) s2 += __shfl_down_sync(0xffffffffu, s2, o);
    if ((tid & 31) == 0) atomicAdd(&g_sq2, s2);
    __syncthreads();
    if (tid < DQ) atomicAdd(&g_sqd[tid], pd[0][tid] + pd[1][tid]);
}

// ---------------------------------------------------------------- loss
__global__ void __launch_bounds__(128) k_loss(float* __restrict__ out_loss) {
    __shared__ double wsum[4];
    int tid = threadIdx.x;
    double c = g_sxd[tid] * g_sqd[tid];
    #pragma unroll
    for (int o = 16; o; o >>= 1) c += __shfl_down_sync(0xffffffffu, c, o);
    if ((tid & 31) == 0) wsum[tid >> 5] = c;
    __syncthreads();
    if (tid == 0) {
        double cross = wsum[0] + wsum[1] + wsum[2] + wsum[3];
        double total = 1024.0 * g_sx2 + 1024.0 * g_sq2 - 2.0 * cross;
        out_loss[0] = (float)(1.25 * (total / (1024.0 * 1024.0 * 128.0)));
    }
}

// ---------------------------------------------------------------- writer
// out[i,j,d] = fl(x[j,d] + fl(q[i,d] - x[j,d]))  -- bit-exact vs reference.
// 256 blocks: (bid & 127) picks the i-slice, (bid >> 7) picks the j-half.
__global__ void __launch_bounds__(256) k_writer(const float* __restrict__ x,
                                                const float* __restrict__ W,
                                                float* __restrict__ out) {
    __shared__ float4 xs[64 * 32];            // 32 KB
    int tid = threadIdx.x;
    int bid = blockIdx.x & 127;
    int jh  = blockIdx.x >> 7;                // 0 or 1: j half
    int g   = bid * 256 + tid;                // 0..32767
    int i   = g >> 5;
    int d4  = g & 31;

    int c = g_ind[i];
    float4 q = ((const float4*)W)[(size_t)c * 32 + d4];

    float4* outp = (float4*)out + (size_t)i * (1024 * 32);
    const float4* xp = (const float4*)x;

    int jbeg = jh * 512, jend = jbeg + 512;
    for (int j0 = jbeg; j0 < jend; j0 += 64) {
        __syncthreads();
        #pragma unroll
        for (int k = 0; k < 8; k++)
            xs[tid + k * 256] = xp[j0 * 32 + tid + k * 256];
        __syncthreads();
        #pragma unroll 4
        for (int jj = 0; jj < 64; jj++) {
            float4 xv = xs[jj * 32 + d4];
            float4 o;
            o.x = __fadd_rn(xv.x, __fsub_rn(q.x, xv.x));
            o.y = __fadd_rn(xv.y, __fsub_rn(q.y, xv.y));
            o.z = __fadd_rn(xv.z, __fsub_rn(q.z, xv.z));
            o.w = __fadd_rn(xv.w, __fsub_rn(q.w, xv.w));
            __stcs(&outp[(size_t)(j0 + jj) * 32 + d4], o);
        }
    }
}

// ---------------------------------------------------------------- launch
extern "C" void kernel_launch(void* const* d_in, const int* in_sizes, int n_in,
                              void* d_out, int out_size) {
    const float* x = (const float*)d_in[0];
    const float* W = (const float*)d_in[1];
    if (n_in >= 2 && in_sizes[0] > in_sizes[1]) {
        x = (const float*)d_in[1];
        W = (const float*)d_in[0];
    }
    float* out = (float*)d_out;
    const long long qcount = 1024LL * 1024LL * 128LL;

    float* pInd  = ((long long)out_size >= qcount + 1024) ? (out + qcount) : nullptr;
    float* pLoss = ((long long)out_size >= qcount + 1025) ? (out + qcount + 1024) : nullptr;

    cudaFuncSetAttribute(k_argmin3, cudaFuncAttributeMaxDynamicSharedMemorySize,
                         (int)sizeof(ArgSmem));
    k_argmin3<<<64 * NSPLIT, 256, sizeof(ArgSmem)>>>(x, W);
    k_merge  <<<1, 1024>>>(pInd);
    if (pLoss) {
        k_sums<<<64, 256>>>(x, W);
        k_loss<<<1, 128>>>(pLoss);
    }
    k_writer <<<256, 256>>>(x, W, out);
}

// round 17
// speedup vs baseline: 2.0584x; 2.0584x over previous
#include <cuda_runtime.h>

#define BQ 1024
#define NQ 8192
#define DQ 128
#define NSPLIT 8

__device__ int    g_ind[BQ];
__device__ float  g_pbest[NSPLIT][BQ];
__device__ int    g_pbidx[NSPLIT][BQ];
__device__ double g_sx2;
__device__ double g_sq2;
__device__ double g_sxd[DQ];
__device__ double g_sqd[DQ];

// ---------------------------------------------------------------- argmin smem
struct ArgSmem {
    float xt[128][36];        // x transposed [k][row], 32 rows (pad 36); 18.4KB
                              // reused after mainloop as sb[32][64] + si[32][64]
    float wt[2][8][512];      // W stage transposed [k][n], double-buffered, K=8; 32KB
    float Cs[32];
    float wpart[32][2];
};
extern __shared__ unsigned char dynsmem[];

// ---------------------------------------------------------------- argmin (8x8 micro-tile)
// Numerics bit-identical to the passing R13..R15 path: per-output single fp32
// accumulator, FFMA over d=0..127 ascending (16 K-stages of 8 per n-tile);
// score = __fsub_rn(C, __fmul_rn(2,acc)); ties -> lowest n; C via the proven
// 64-thread float2/shuffle tree. 8x8 micro-tile: 4 LDS.128 per 64 FMA -> FMA-bound.
// Grid 256 = 32 rowblocks x 8 n-splits; block scans 2 tiles of 512 codes.
__global__ void __launch_bounds__(256, 2) k_argmin4(const float* __restrict__ x,
                                                    const float* __restrict__ W) {
    ArgSmem& sm = *reinterpret_cast<ArgSmem*>(dynsmem);
    int rb = blockIdx.x & 31;
    int cs = blockIdx.x >> 5;
    int r0 = rb * 32;
    int nbase = cs * 1024;
    int tid = threadIdx.x;
    int rg = tid >> 6, cg = tid & 63;

    // ---- C for 32 rows (bit-identical 64-thread tree per row) ----
    {
        int grp = tid >> 6;
        int t64 = tid & 63;
        #pragma unroll
        for (int pass = 0; pass < 8; pass++) {
            int row32 = pass * 4 + grp;
            const float2* xp = (const float2*)(x + (size_t)(r0 + row32) * DQ);
            float2 v = xp[t64];
            float p = __fadd_rn(__fmul_rn(v.x, v.x), __fmul_rn(v.y, v.y));
            #pragma unroll
            for (int o = 16; o; o >>= 1)
                p = __fadd_rn(p, __shfl_down_sync(0xffffffffu, p, o));
            if ((t64 & 31) == 0) sm.wpart[row32][t64 >> 5] = p;
        }
    }
    // ---- stage x transposed: xt[d][r] = x[r0+r][d] ----
    for (int i = tid; i < 32 * 128; i += 256) {
        int r = i >> 7, d = i & 127;
        sm.xt[d][r] = x[(size_t)(r0 + r) * DQ + d];
    }
    __syncthreads();
    if (tid < 32) sm.Cs[tid] = __fadd_rn(sm.wpart[tid][0], sm.wpart[tid][1]);
    __syncthreads();

    float best[8];
    int   bidx[8];
    #pragma unroll
    for (int r = 0; r < 8; r++) { best[r] = 3.4e38f; bidx[r] = 0; }

    float acc[8][8];
    float4 rv[4];

    // preload stage u=0: tile 0, k 0..7; thread owns W rows nbase+tid, nbase+256+tid
    {
        const float4* wa = (const float4*)(W + (size_t)(nbase + tid) * DQ);
        const float4* wb = (const float4*)(W + (size_t)(nbase + 256 + tid) * DQ);
        rv[0] = wa[0]; rv[1] = wa[1];
        rv[2] = wb[0]; rv[3] = wb[1];
        #pragma unroll
        for (int kk = 0; kk < 8; kk++) {
            sm.wt[0][kk][tid]       = (kk < 4) ? (&rv[0].x)[kk] : (&rv[1].x)[kk - 4];
            sm.wt[0][kk][256 + tid] = (kk < 4) ? (&rv[2].x)[kk] : (&rv[3].x)[kk - 4];
        }
    }
    __syncthreads();

    for (int u = 0; u < 32; u++) {             // u = tile*16 + stage; K-stage = 8
        int t = u >> 4, s = u & 15;
        int buf = u & 1;
        if (s == 0) {
            #pragma unroll
            for (int a = 0; a < 8; a++)
                #pragma unroll
                for (int b = 0; b < 8; b++) acc[a][b] = 0.f;
        }
        if (u < 31) {                          // LDG next stage (32B k-chunk per n)
            int u1 = u + 1;
            int t1 = u1 >> 4, s1 = u1 & 15;
            const float4* wa = (const float4*)(W + (size_t)(nbase + t1 * 512 + tid) * DQ + s1 * 8);
            const float4* wb = (const float4*)(W + (size_t)(nbase + t1 * 512 + 256 + tid) * DQ + s1 * 8);
            rv[0] = wa[0]; rv[1] = wa[1];
            rv[2] = wb[0]; rv[3] = wb[1];
        }
        int k0 = s * 8;
        #pragma unroll
        for (int kk = 0; kk < 8; kk++) {
            float4 xa0 = *(const float4*)&sm.xt[k0 + kk][rg * 8];
            float4 xa1 = *(const float4*)&sm.xt[k0 + kk][rg * 8 + 4];
            float4 wb0 = *(const float4*)&sm.wt[buf][kk][cg * 4];
            float4 wb1 = *(const float4*)&sm.wt[buf][kk][256 + cg * 4];
            const float xr[8] = {xa0.x, xa0.y, xa0.z, xa0.w, xa1.x, xa1.y, xa1.z, xa1.w};
            const float wc[8] = {wb0.x, wb0.y, wb0.z, wb0.w, wb1.x, wb1.y, wb1.z, wb1.w};
            #pragma unroll
            for (int ri = 0; ri < 8; ri++)
                #pragma unroll
                for (int ci = 0; ci < 8; ci++)
                    acc[ri][ci] = fmaf(xr[ri], wc[ci], acc[ri][ci]);
        }
        if (s == 15) {                         // tile done -> scores + best update
            int n0 = nbase + t * 512;
            #pragma unroll
            for (int ri = 0; ri < 8; ri++) {
                float Cv = sm.Cs[rg * 8 + ri];
                #pragma unroll
                for (int ci = 0; ci < 8; ci++) {
                    // ci 0..3 -> n0+4cg+ci ; ci 4..7 -> n0+256+4cg+(ci-4): ascending
                    int n = n0 + ((ci < 4) ? (cg * 4 + ci) : (256 + cg * 4 + ci - 4));
                    float sc = __fsub_rn(Cv, __fmul_rn(2.0f, acc[ri][ci]));
                    if (sc < best[ri]) { best[ri] = sc; bidx[ri] = n; }
                }
            }
        }
        if (u < 31) {                          // STS -> buffer NOT being read
            int nb = (u + 1) & 1;
            #pragma unroll
            for (int kk = 0; kk < 8; kk++) {
                sm.wt[nb][kk][tid]       = (kk < 4) ? (&rv[0].x)[kk] : (&rv[1].x)[kk - 4];
                sm.wt[nb][kk][256 + tid] = (kk < 4) ? (&rv[2].x)[kk] : (&rv[3].x)[kk - 4];
            }
        }
        __syncthreads();                       // single barrier per stage
    }

    // ---- reduction: reuse xt region (dead after mainloop) ----
    float* sbf = (float*)sm.xt;                // sb[32][64]
    int*   sif = (int*)(sbf + 32 * 64);        // si[32][64]
    #pragma unroll
    for (int ri = 0; ri < 8; ri++) {
        sbf[(rg * 8 + ri) * 64 + cg] = best[ri];
        sif[(rg * 8 + ri) * 64 + cg] = bidx[ri];
    }
    __syncthreads();
    if (tid < 32) {
        float bv = sbf[tid * 64]; int bi = sif[tid * 64];
        #pragma unroll 8
        for (int tt = 1; tt < 64; tt++) {
            float v = sbf[tid * 64 + tt]; int ii = sif[tid * 64 + tt];
            if (v < bv || (v == bv && ii < bi)) { bv = v; bi = ii; }
        }
        g_pbest[cs][r0 + tid] = bv;
        g_pbidx[cs][r0 + tid] = bi;
    }
}

// ---------------------------------------------------------------- merge + zero
__global__ void __launch_bounds__(1024) k_merge(float* __restrict__ out_ind) {
    int i = threadIdx.x;
    float bv = g_pbest[0][i]; int bi = g_pbidx[0][i];
    #pragma unroll
    for (int cs = 1; cs < NSPLIT; cs++) {
        float v = g_pbest[cs][i]; int ii = g_pbidx[cs][i];
        if (v < bv || (v == bv && ii < bi)) { bv = v; bi = ii; }
    }
    g_ind[i] = bi;
    if (out_ind) out_ind[i] = (float)bi;
    if (i < DQ) { g_sxd[i] = 0.0; g_sqd[i] = 0.0; }
    if (i == 0) { g_sx2 = 0.0; g_sq2 = 0.0; }
}

// ---------------------------------------------------------------- sums (64 blocks)
__global__ void __launch_bounds__(256) k_sums(const float* __restrict__ x,
                                              const float* __restrict__ W) {
    __shared__ double pd[2][DQ];
    __shared__ int sInd[16];
    int r0  = blockIdx.x * 16;
    int tid = threadIdx.x;
    int d = tid & 127, h = tid >> 7;
    if (tid < 16) sInd[tid] = g_ind[r0 + tid];
    __syncthreads();

    double sd = 0.0, s2 = 0.0;
    #pragma unroll
    for (int rr = 0; rr < 8; rr++) {
        double v = (double)x[(size_t)(r0 + h * 8 + rr) * DQ + d];
        sd += v; s2 += v * v;
    }
    pd[h][d] = sd;
    #pragma unroll
    for (int o = 16; o; o >>= 1) s2 += __shfl_down_sync(0xffffffffu, s2, o);
    if ((tid & 31) == 0) atomicAdd(&g_sx2, s2);
    __syncthreads();
    if (tid < DQ) atomicAdd(&g_sxd[tid], pd[0][tid] + pd[1][tid]);
    __syncthreads();

    sd = 0.0; s2 = 0.0;
    #pragma unroll
    for (int rr = 0; rr < 8; rr++) {
        int c = sInd[h * 8 + rr];
        double v = (double)W[(size_t)c * DQ + d];
        sd += v; s2 += v * v;
    }
    pd[h][d] = sd;
    #pragma unroll
    for (int o = 16; o; o >>= 1) s2 += __shfl_down_sync(0xffffffffu, s2, o);
    if ((tid & 31) == 0) atomicAdd(&g_sq2, s2);
    __syncthreads();
    if (tid < DQ) atomicAdd(&g_sqd[tid], pd[0][tid] + pd[1][tid]);
}

// ---------------------------------------------------------------- loss
__global__ void __launch_bounds__(128) k_loss(float* __restrict__ out_loss) {
    __shared__ double wsum[4];
    int tid = threadIdx.x;
    double c = g_sxd[tid] * g_sqd[tid];
    #pragma unroll
    for (int o = 16; o; o >>= 1) c += __shfl_down_sync(0xffffffffu, c, o);
    if ((tid & 31) == 0) wsum[tid >> 5] = c;
    __syncthreads();
    if (tid == 0) {
        double cross = wsum[0] + wsum[1] + wsum[2] + wsum[3];
        double total = 1024.0 * g_sx2 + 1024.0 * g_sq2 - 2.0 * cross;
        out_loss[0] = (float)(1.25 * (total / (1024.0 * 1024.0 * 128.0)));
    }
}

// ---------------------------------------------------------------- writer
// out[i,j,d] = fl(x[j,d] + fl(q[i,d] - x[j,d]))  -- bit-exact vs reference.
// 256 blocks: (bid & 127) -> i-slice, (bid >> 7) -> j-half; all 148 SMs busy.
__global__ void __launch_bounds__(256) k_writer(const float* __restrict__ x,
                                                const float* __restrict__ W,
                                                float* __restrict__ out) {
    __shared__ float4 xs[64 * 32];            // 32 KB
    int tid = threadIdx.x;
    int bid = blockIdx.x & 127;
    int jh  = blockIdx.x >> 7;
    int g   = bid * 256 + tid;                // 0..32767
    int i   = g >> 5;
    int d4  = g & 31;

    int c = g_ind[i];
    float4 q = ((const float4*)W)[(size_t)c * 32 + d4];

    float4* outp = (float4*)out + (size_t)i * (1024 * 32);
    const float4* xp = (const float4*)x;

    int jbeg = jh * 512, jend = jbeg + 512;
    for (int j0 = jbeg; j0 < jend; j0 += 64) {
        __syncthreads();
        #pragma unroll
        for (int k = 0; k < 8; k++)
            xs[tid + k * 256] = xp[j0 * 32 + tid + k * 256];
        __syncthreads();
        #pragma unroll 4
        for (int jj = 0; jj < 64; jj++) {
            float4 xv = xs[jj * 32 + d4];
            float4 o;
            o.x = __fadd_rn(xv.x, __fsub_rn(q.x, xv.x));
            o.y = __fadd_rn(xv.y, __fsub_rn(q.y, xv.y));
            o.z = __fadd_rn(xv.z, __fsub_rn(q.z, xv.z));
            o.w = __fadd_rn(xv.w, __fsub_rn(q.w, xv.w));
            __stcs(&outp[(size_t)(j0 + jj) * 32 + d4], o);
        }
    }
}

// ---------------------------------------------------------------- launch
extern "C" void kernel_launch(void* const* d_in, const int* in_sizes, int n_in,
                              void* d_out, int out_size) {
    const float* x = (const float*)d_in[0];
    const float* W = (const float*)d_in[1];
    if (n_in >= 2 && in_sizes[0] > in_sizes[1]) {
        x = (const float*)d_in[1];
        W = (const float*)d_in[0];
    }
    float* out = (float*)d_out;
    const long long qcount = 1024LL * 1024LL * 128LL;

    float* pInd  = ((long long)out_size >= qcount + 1024) ? (out + qcount) : nullptr;
    float* pLoss = ((long long)out_size >= qcount + 1025) ? (out + qcount + 1024) : nullptr;

    cudaFuncSetAttribute(k_argmin4, cudaFuncAttributeMaxDynamicSharedMemorySize,
                         (int)sizeof(ArgSmem));
    k_argmin4<<<32 * NSPLIT, 256, sizeof(ArgSmem)>>>(x, W);
    k_merge  <<<1, 1024>>>(pInd);
    if (pLoss) {
        k_sums<<<64, 256>>>(x, W);
        k_loss<<<1, 128>>>(pLoss);
    }
    k_writer <<<256, 256>>>(x, W, out);
}